// round 1
// baseline (speedup 1.0000x reference)
#include <cuda_runtime.h>
#include <stdint.h>

#define NC    1000      // num classes
#define DD    1024      // feature dim
#define D4    256       // feature dim in float4
#define BQ    32768     // labels per batch (samples = 2*BQ)
#define MAXK  1024      // per-class index list capacity (Poisson mean ~33)
#define MOM   0.9f

// ---- scratch (no allocations allowed) ----
__device__ int   g_is64;
__device__ int   g_counts[NC];
__device__ int   g_idx[NC * MAXK];
__device__ float g_loss;
__device__ int   g_present;

// ---------------------------------------------------------------------------
// K0: init + label-width probe.
//  - zero per-class counts and the scalar accumulators (graph replays need this)
//  - detect whether labels are int64 or int32: reading int32-packed labels as
//    int64 combines two labels (value >= 2^32 unless the odd one is 0); with
//    64 probes the misdetection probability is (1/1000)^64 ~ 0.
// ---------------------------------------------------------------------------
__global__ void k_init(const long long* __restrict__ l64) {
    int t = threadIdx.x;
    for (int c = t; c < NC; c += blockDim.x) g_counts[c] = 0;
    if (t == 0) {
        int ok = 1;
        #pragma unroll 8
        for (int k = 0; k < 64; k++) {
            long long v = l64[k];
            if (v < 0 || v >= NC) ok = 0;
        }
        g_is64 = ok;
        g_loss = 0.0f;
        g_present = 0;
    }
}

// ---------------------------------------------------------------------------
// K1: counting-sort scatter. Builds per-class sample index lists.
//     32768 atomicAdds to 1000 counters -> trivial contention, µs-scale.
// ---------------------------------------------------------------------------
__global__ void k_scatter(const int* __restrict__ l32) {
    const int shift = g_is64;   // 1 => int64 labels: low word at index 2*j
    int stride = gridDim.x * blockDim.x;
    for (int j = blockIdx.x * blockDim.x + threadIdx.x; j < BQ; j += stride) {
        int c = l32[j << shift];
        if (c >= 0 && c < NC) {
            int pos = atomicAdd(&g_counts[c], 1);
            if (pos < MAXK) g_idx[c * MAXK + pos] = j;
        }
    }
}

// ---------------------------------------------------------------------------
// block reduction helper (256 threads)
// ---------------------------------------------------------------------------
__device__ __forceinline__ float block_reduce(float v, float* sred) {
    __syncthreads();                         // protect sred reuse
    #pragma unroll
    for (int o = 16; o; o >>= 1) v += __shfl_down_sync(0xffffffffu, v, o);
    int w = threadIdx.x >> 5;
    if ((threadIdx.x & 31) == 0) sred[w] = v;
    __syncthreads();
    if (w == 0) {
        v = (threadIdx.x < 8) ? sred[threadIdx.x] : 0.0f;
        #pragma unroll
        for (int o = 4; o; o >>= 1) v += __shfl_down_sync(0xffffffffu, v, o);
        if (threadIdx.x == 0) sred[0] = v;
    }
    __syncthreads();
    return sred[0];
}

// ---------------------------------------------------------------------------
// K2: main fused kernel. One block per class.
//  - gather-sum the class's rows of x (both crops) into registers
//  - momentum update + L2 normalize + squared-distance loss, all in-block
//  - the 256 MB of x is read exactly once, fully coalesced (4 KB row bursts)
// ---------------------------------------------------------------------------
__global__ void __launch_bounds__(256, 4)
k_main(const float4* __restrict__ x4,
       const float4* __restrict__ ci4,
       const float4* __restrict__ cs4) {
    const int c = blockIdx.x;
    int cnt = g_counts[c];
    if (cnt == 0) return;                 // absent class: loss contribution 0
    if (cnt > MAXK) cnt = MAXK;           // defensive (statistically impossible)

    const int t = threadIdx.x;
    __shared__ int   sidx[MAXK];
    __shared__ float sred[32];

    for (int k = t; k < cnt; k += 256) sidx[k] = g_idx[c * MAXK + k];
    __syncthreads();

    // gather-reduce: 2 independent loads per sample, unrolled x2 -> 4 in flight
    float4 acc0 = make_float4(0.f, 0.f, 0.f, 0.f);
    float4 acc1 = make_float4(0.f, 0.f, 0.f, 0.f);
    int k = 0;
    for (; k + 2 <= cnt; k += 2) {
        int j0 = sidx[k], j1 = sidx[k + 1];
        float4 a = x4[j0 * D4 + t];
        float4 b = x4[(j0 + BQ) * D4 + t];
        float4 e = x4[j1 * D4 + t];
        float4 f = x4[(j1 + BQ) * D4 + t];
        acc0.x += a.x + b.x; acc0.y += a.y + b.y;
        acc0.z += a.z + b.z; acc0.w += a.w + b.w;
        acc1.x += e.x + f.x; acc1.y += e.y + f.y;
        acc1.z += e.z + f.z; acc1.w += e.w + f.w;
    }
    if (k < cnt) {
        int j0 = sidx[k];
        float4 a = x4[j0 * D4 + t];
        float4 b = x4[(j0 + BQ) * D4 + t];
        acc0.x += a.x + b.x; acc0.y += a.y + b.y;
        acc0.z += a.z + b.z; acc0.w += a.w + b.w;
    }
    acc0.x += acc1.x; acc0.y += acc1.y; acc0.z += acc1.z; acc0.w += acc1.w;

    // per-class mean, momentum EMA
    const float invn = 1.0f / (2.0f * (float)cnt);
    float4 ci = ci4[c * D4 + t];
    float4 u;
    u.x = ci.x * MOM + acc0.x * invn * (1.0f - MOM);
    u.y = ci.y * MOM + acc0.y * invn * (1.0f - MOM);
    u.z = ci.z * MOM + acc0.z * invn * (1.0f - MOM);
    u.w = ci.w * MOM + acc0.w * invn * (1.0f - MOM);

    // L2 norm over D (block reduction)
    float nsq = u.x * u.x + u.y * u.y + u.z * u.z + u.w * u.w;
    float total = block_reduce(nsq, sred);
    float rnorm = 1.0f / sqrtf(total);

    // squared distance to center_skt
    float4 cs = cs4[c * D4 + t];
    float dx = u.x * rnorm - cs.x;
    float dy = u.y * rnorm - cs.y;
    float dz = u.z * rnorm - cs.z;
    float dw = u.w * rnorm - cs.w;
    float ls = dx * dx + dy * dy + dz * dz + dw * dw;
    float lsum = block_reduce(ls, sred);

    if (t == 0) {
        atomicAdd(&g_loss, lsum);
        atomicAdd(&g_present, 1);
    }
}

// ---------------------------------------------------------------------------
// K3: finalize
// ---------------------------------------------------------------------------
__global__ void k_final(float* __restrict__ out) {
    int n = g_present;
    out[0] = g_loss / (float)(n > 0 ? n : 1);
}

extern "C" void kernel_launch(void* const* d_in, const int* in_sizes, int n_in,
                              void* d_out, int out_size) {
    const float4*     x4  = (const float4*)d_in[0];
    const float4*     ci4 = (const float4*)d_in[1];
    const float4*     cs4 = (const float4*)d_in[2];
    const void*       l   = d_in[3];

    k_init<<<1, 1024>>>((const long long*)l);
    k_scatter<<<64, 512>>>((const int*)l);
    k_main<<<NC, 256>>>(x4, ci4, cs4);
    k_final<<<1, 1>>>((float*)d_out);
}

// round 2
// speedup vs baseline: 1.1896x; 1.1896x over previous
#include <cuda_runtime.h>
#include <stdint.h>

#define NC    1000      // num classes
#define D4    256       // feature dim in float4 (1024 floats)
#define BQ    32768     // labels per batch (samples = 2*BQ)
#define MAXK  1024      // per-class index list capacity (Poisson mean ~33)
#define MOM   0.9f

// ---- scratch (device globals; zero-initialized at module load) ----
__device__ int   g_counts[NC];
__device__ int   g_idx[NC * MAXK];
__device__ float g_loss;
__device__ int   g_present;
__device__ int   g_done;

// ---------------------------------------------------------------------------
// K1: counting-sort scatter with embedded label-width probe.
//  Probe: read the first 64 labels as int64. If labels are really int32, a
//  64-bit read packs two labels; the high word is a label in [0,1000) with
//  prob 1/1000 per pair, so P(all 64 look valid) = (1/1000)^64 ~ 0.
//  Each block probes independently (warp ballot, ~2 loads of latency).
// ---------------------------------------------------------------------------
__global__ void k_scatter(const int* __restrict__ l32,
                          const long long* __restrict__ l64) {
    __shared__ int sh_shift;
    if (threadIdx.x < 32) {
        int ok = 1;
        #pragma unroll
        for (int k = threadIdx.x; k < 64; k += 32) {
            long long v = l64[k];
            if (v < 0 || v >= NC) ok = 0;
        }
        unsigned m = __ballot_sync(0xffffffffu, ok);
        if (threadIdx.x == 0) sh_shift = (m == 0xffffffffu) ? 1 : 0;
    }
    __syncthreads();
    const int shift = sh_shift;           // 1 => int64: low word at index 2*j
    int stride = gridDim.x * blockDim.x;
    for (int j = blockIdx.x * blockDim.x + threadIdx.x; j < BQ; j += stride) {
        int c = l32[j << shift];
        if ((unsigned)c < (unsigned)NC) {
            int pos = atomicAdd(&g_counts[c], 1);
            if (pos < MAXK) g_idx[c * MAXK + pos] = j;
        }
    }
}

// ---------------------------------------------------------------------------
// K2: fused main kernel. One 128-thread block per class, single wave
//     (8 blocks/SM * 148 SMs = 1184 slots >= 1000 blocks).
//  Each thread owns float4 columns t and t+128 -> 8 independent LDG.128 in
//  flight per thread (2 samples x 2 crops x 2 cols per iteration).
//  Fused: per-class mean, momentum EMA, L2 normalize, squared distance,
//  global loss accumulation, counter reset, and last-block finalize.
// ---------------------------------------------------------------------------
__global__ void __launch_bounds__(128, 8)
k_main(const float4* __restrict__ x4,
       const float4* __restrict__ ci4,
       const float4* __restrict__ cs4,
       float* __restrict__ out) {
    const int c = blockIdx.x;
    const int t = threadIdx.x;
    __shared__ int   sidx[MAXK];
    __shared__ float sred[4];

    int cnt = g_counts[c];
    if (cnt > MAXK) cnt = MAXK;           // defensive (statistically impossible)

    if (cnt > 0) {
        if (t == 0) g_counts[c] = 0;      // reset for next graph replay
        for (int k = t; k < cnt; k += 128) sidx[k] = g_idx[c * MAXK + k];
        __syncthreads();

        const float4* xa = x4 + t;        // column t
        const float4* xb = x4 + t + 128;  // column t+128
        float4 aA = make_float4(0.f,0.f,0.f,0.f);   // col t,   sample stream 0
        float4 bA = make_float4(0.f,0.f,0.f,0.f);   // col t+128, stream 0
        float4 aB = make_float4(0.f,0.f,0.f,0.f);   // col t,   sample stream 1
        float4 bB = make_float4(0.f,0.f,0.f,0.f);   // col t+128, stream 1

        int k = 0;
        for (; k + 2 <= cnt; k += 2) {
            int j0 = sidx[k], j1 = sidx[k + 1];
            float4 p0 = __ldcs(xa + (size_t)j0 * D4);
            float4 q0 = __ldcs(xb + (size_t)j0 * D4);
            float4 p1 = __ldcs(xa + (size_t)(j0 + BQ) * D4);
            float4 q1 = __ldcs(xb + (size_t)(j0 + BQ) * D4);
            float4 p2 = __ldcs(xa + (size_t)j1 * D4);
            float4 q2 = __ldcs(xb + (size_t)j1 * D4);
            float4 p3 = __ldcs(xa + (size_t)(j1 + BQ) * D4);
            float4 q3 = __ldcs(xb + (size_t)(j1 + BQ) * D4);
            aA.x += p0.x + p1.x; aA.y += p0.y + p1.y; aA.z += p0.z + p1.z; aA.w += p0.w + p1.w;
            bA.x += q0.x + q1.x; bA.y += q0.y + q1.y; bA.z += q0.z + q1.z; bA.w += q0.w + q1.w;
            aB.x += p2.x + p3.x; aB.y += p2.y + p3.y; aB.z += p2.z + p3.z; aB.w += p2.w + p3.w;
            bB.x += q2.x + q3.x; bB.y += q2.y + q3.y; bB.z += q2.z + q3.z; bB.w += q2.w + q3.w;
        }
        if (k < cnt) {
            int j0 = sidx[k];
            float4 p0 = __ldcs(xa + (size_t)j0 * D4);
            float4 q0 = __ldcs(xb + (size_t)j0 * D4);
            float4 p1 = __ldcs(xa + (size_t)(j0 + BQ) * D4);
            float4 q1 = __ldcs(xb + (size_t)(j0 + BQ) * D4);
            aA.x += p0.x + p1.x; aA.y += p0.y + p1.y; aA.z += p0.z + p1.z; aA.w += p0.w + p1.w;
            bA.x += q0.x + q1.x; bA.y += q0.y + q1.y; bA.z += q0.z + q1.z; bA.w += q0.w + q1.w;
        }
        aA.x += aB.x; aA.y += aB.y; aA.z += aB.z; aA.w += aB.w;
        bA.x += bB.x; bA.y += bB.y; bA.z += bB.z; bA.w += bB.w;

        // per-class mean + momentum EMA (both columns)
        const float s = (1.0f - MOM) / (2.0f * (float)cnt);
        float4 ci_a = ci4[c * D4 + t];
        float4 ci_b = ci4[c * D4 + t + 128];
        float4 ua, ub;
        ua.x = ci_a.x * MOM + aA.x * s;  ua.y = ci_a.y * MOM + aA.y * s;
        ua.z = ci_a.z * MOM + aA.z * s;  ua.w = ci_a.w * MOM + aA.w * s;
        ub.x = ci_b.x * MOM + bA.x * s;  ub.y = ci_b.y * MOM + bA.y * s;
        ub.z = ci_b.z * MOM + bA.z * s;  ub.w = ci_b.w * MOM + bA.w * s;

        // L2 norm over D (block reduction, 4 warps)
        float nsq = ua.x*ua.x + ua.y*ua.y + ua.z*ua.z + ua.w*ua.w
                  + ub.x*ub.x + ub.y*ub.y + ub.z*ub.z + ub.w*ub.w;
        #pragma unroll
        for (int o = 16; o; o >>= 1) nsq += __shfl_down_sync(0xffffffffu, nsq, o);
        if ((t & 31) == 0) sred[t >> 5] = nsq;
        __syncthreads();
        float total = sred[0] + sred[1] + sred[2] + sred[3];
        float rnorm = rsqrtf(total);

        // squared distance to center_skt
        float4 cs_a = cs4[c * D4 + t];
        float4 cs_b = cs4[c * D4 + t + 128];
        float dx = ua.x * rnorm - cs_a.x, dy = ua.y * rnorm - cs_a.y;
        float dz = ua.z * rnorm - cs_a.z, dw = ua.w * rnorm - cs_a.w;
        float ls = dx*dx + dy*dy + dz*dz + dw*dw;
        dx = ub.x * rnorm - cs_b.x; dy = ub.y * rnorm - cs_b.y;
        dz = ub.z * rnorm - cs_b.z; dw = ub.w * rnorm - cs_b.w;
        ls += dx*dx + dy*dy + dz*dz + dw*dw;
        #pragma unroll
        for (int o = 16; o; o >>= 1) ls += __shfl_down_sync(0xffffffffu, ls, o);
        __syncthreads();                  // protect sred reuse
        if ((t & 31) == 0) sred[t >> 5] = ls;
        __syncthreads();
        if (t == 0) {
            atomicAdd(&g_loss, sred[0] + sred[1] + sred[2] + sred[3]);
            atomicAdd(&g_present, 1);
        }
    }

    // last-block finalize (every block, including empty classes, arrives here)
    if (t == 0) {
        __threadfence();
        if (atomicAdd(&g_done, 1) == NC - 1) {
            float L = atomicAdd(&g_loss, 0.0f);      // L2-coherent read
            int   n = atomicAdd(&g_present, 0);
            out[0] = L / (float)(n > 0 ? n : 1);
            g_done = 0; g_loss = 0.0f; g_present = 0;  // reset for next replay
            __threadfence();
        }
    }
}

extern "C" void kernel_launch(void* const* d_in, const int* in_sizes, int n_in,
                              void* d_out, int out_size) {
    const float4* x4  = (const float4*)d_in[0];
    const float4* ci4 = (const float4*)d_in[1];
    const float4* cs4 = (const float4*)d_in[2];
    const void*   l   = d_in[3];

    k_scatter<<<64, 512>>>((const int*)l, (const long long*)l);
    k_main<<<NC, 128>>>(x4, ci4, cs4, (float*)d_out);
}